// round 2
// baseline (speedup 1.0000x reference)
#include <cuda_runtime.h>

#define THREADS 256
#define CHUNK   8192
#define MAX_NB  32768
#define NWARPS  (THREADS / 32)

// Scratch (device globals — no allocations allowed)
__device__ unsigned g_cnt[MAX_NB];      // per-block positive counts
__device__ unsigned g_off[MAX_NB];      // exclusive prefix of counts
__device__ unsigned g_total;            // total positives P
__device__ float    g_partial[MAX_NB];  // per-block loss partials

__device__ __forceinline__ unsigned warp_incl_scan(unsigned v) {
#pragma unroll
    for (int o = 1; o < 32; o <<= 1) {
        unsigned u = __shfl_up_sync(0xffffffffu, v, o);
        if ((threadIdx.x & 31) >= (unsigned)o) v += u;
    }
    return v;
}

// ---------------------------------------------------------------------------
// Kernel 1: per-block positive counts (reads score once: 64 MB)
// ---------------------------------------------------------------------------
__global__ void k_count(const float* __restrict__ score, int n) {
    const int t = threadIdx.x;
    const long long base = (long long)blockIdx.x * CHUNK;
    const float4* __restrict__ s4 = (const float4*)score;
    unsigned cnt = 0;
#pragma unroll
    for (int i = 0; i < CHUNK / 4 / THREADS; i++) {
        long long vi = base / 4 + (long long)i * THREADS + t;
        long long e0 = vi * 4;
        if (e0 + 3 < n) {
            float4 v = __ldg(&s4[vi]);
            cnt += (v.x > 0.f) + (v.y > 0.f) + (v.z > 0.f) + (v.w > 0.f);
        } else {
#pragma unroll
            for (int j = 0; j < 4; j++)
                if (e0 + j < n) cnt += (score[e0 + j] > 0.f);
        }
    }
    // block reduce
#pragma unroll
    for (int o = 16; o > 0; o >>= 1) cnt += __shfl_down_sync(0xffffffffu, cnt, o);
    __shared__ unsigned ws[NWARPS];
    if ((t & 31) == 0) ws[t >> 5] = cnt;
    __syncthreads();
    if (t == 0) {
        unsigned s = 0;
#pragma unroll
        for (int w = 0; w < NWARPS; w++) s += ws[w];
        g_cnt[blockIdx.x] = s;
    }
}

// ---------------------------------------------------------------------------
// Kernel 2: single-block exclusive scan of block counts + total (tiny)
// ---------------------------------------------------------------------------
__global__ void k_scan(int nb) {
    const int t = threadIdx.x;           // 1024 threads
    __shared__ unsigned wsums[32];
    __shared__ unsigned wexcl[32];
    __shared__ unsigned tile_total;
    unsigned carry = 0;
    for (int tb = 0; tb < nb; tb += 1024) {
        int i = tb + t;
        unsigned v = (i < nb) ? g_cnt[i] : 0u;
        unsigned inc = warp_incl_scan(v);
        if ((t & 31) == 31) wsums[t >> 5] = inc;
        __syncthreads();
        if (t < 32) {
            unsigned x = wsums[t];        // 32 warps exactly
            unsigned xi = warp_incl_scan(x);
            wexcl[t] = xi - x;
            if (t == 31) tile_total = xi;
        }
        __syncthreads();
        if (i < nb) g_off[i] = carry + wexcl[t >> 5] + (inc - v);
        carry += tile_total;
        __syncthreads();
    }
    if (t == 0) g_total = carry;
}

// ---------------------------------------------------------------------------
// Kernel 3: main pass — local rescan + loss terms (reads 128 MB)
// ---------------------------------------------------------------------------
__global__ void k_main(const float* __restrict__ pred,
                       const float* __restrict__ score, int n) {
    const int t = threadIdx.x;
    const int b = blockIdx.x;
    const long long base = (long long)b * CHUNK;

    __shared__ unsigned wsums[NWARPS];
    __shared__ unsigned wexcl[NWARPS];
    __shared__ unsigned pass_total;

    unsigned carry = g_off[b];
    const float Tf = (float)g_total;          // P, exact (< 2^24)
    const float S  = 1.0f / Tf;               // s at positive positions
    const float inv_sum_s = 1.0f / (Tf * S);  // sum(s) ~ 1.0 (faithful)
    float acc = 0.f;

    const float4* __restrict__ s4 = (const float4*)score;
    const float4* __restrict__ p4 = (const float4*)pred;

#pragma unroll 1
    for (int pass = 0; pass < CHUNK / (THREADS * 4); pass++) {
        long long e0 = base + (long long)pass * (THREADS * 4) + t * 4;
        float ss[4], pp[4];
        if (e0 + 3 < n) {
            float4 v = __ldg(&s4[e0 >> 2]);
            float4 w = __ldg(&p4[e0 >> 2]);
            ss[0] = v.x; ss[1] = v.y; ss[2] = v.z; ss[3] = v.w;
            pp[0] = w.x; pp[1] = w.y; pp[2] = w.z; pp[3] = w.w;
        } else {
#pragma unroll
            for (int j = 0; j < 4; j++) {
                long long gi = e0 + j;
                ss[j] = (gi < n) ? score[gi] : 0.f;
                pp[j] = (gi < n) ? pred[gi]  : 0.f;
            }
        }
        unsigned bit[4];
        unsigned c = 0;
#pragma unroll
        for (int j = 0; j < 4; j++) { bit[j] = ss[j] > 0.f; c += bit[j]; }

        unsigned winc = warp_incl_scan(c);
        if ((t & 31) == 31) wsums[t >> 5] = winc;
        __syncthreads();
        if (t < 32) {
            unsigned x  = (t < NWARPS) ? wsums[t] : 0u;
            unsigned xi = warp_incl_scan(x);
            if (t < NWARPS) wexcl[t] = xi - x;
            if (t == NWARPS - 1) pass_total = xi;
        }
        __syncthreads();

        unsigned k = carry + wexcl[t >> 5] + (winc - c);  // exclusive before e0
#pragma unroll
        for (int j = 0; j < 4; j++) {
            long long gi = e0 + j;
            if (gi < n) {
                k += bit[j];                               // inclusive rank
                float p = pp[j] * inv_sum_s;
                float term;
                if (bit[j]) {
                    float kf = (float)k + 1.0f;            // k+1 >= 2
                    float a = __fdividef(p, kf) - __fdividef(S, __log2f(kf));
                    term = a * a;
                } else {
                    // P + m + 1 = Tf + (gi + 2 - k)
                    float d = Tf + (float)(gi + 2 - (long long)k);
                    float q = __fdividef(p, d);
                    term = q * q;
                }
                acc += term;
            }
        }
        carry += pass_total;
        __syncthreads();
    }

    // deterministic block reduce of acc
#pragma unroll
    for (int o = 16; o > 0; o >>= 1) acc += __shfl_down_sync(0xffffffffu, acc, o);
    __shared__ float facc[NWARPS];
    if ((t & 31) == 0) facc[t >> 5] = acc;
    __syncthreads();
    if (t == 0) {
        float s = 0.f;
#pragma unroll
        for (int w = 0; w < NWARPS; w++) s += facc[w];
        g_partial[b] = s;
    }
}

// ---------------------------------------------------------------------------
// Kernel 4: deterministic final reduction of block partials
// ---------------------------------------------------------------------------
__global__ void k_reduce(float* __restrict__ out, int nb) {
    const int t = threadIdx.x;            // 1024 threads
    float a = 0.f;
    for (int i = t; i < nb; i += 1024) a += g_partial[i];
#pragma unroll
    for (int o = 16; o > 0; o >>= 1) a += __shfl_down_sync(0xffffffffu, a, o);
    __shared__ float sh[32];
    if ((t & 31) == 0) sh[t >> 5] = a;
    __syncthreads();
    if (t == 0) {
        float s = 0.f;
#pragma unroll
        for (int w = 0; w < 32; w++) s += sh[w];
        out[0] = s;
    }
}

// ---------------------------------------------------------------------------
extern "C" void kernel_launch(void* const* d_in, const int* in_sizes, int n_in,
                              void* d_out, int out_size) {
    const float* pred  = (const float*)d_in[0];  // predict_score
    const float* score = (const float*)d_in[1];  // score
    int n  = in_sizes[0];
    int nb = (n + CHUNK - 1) / CHUNK;            // 2048 for N=16777216

    k_count<<<nb, THREADS>>>(score, n);
    k_scan<<<1, 1024>>>(nb);
    k_main<<<nb, THREADS>>>(pred, score, n);
    k_reduce<<<1, 1024>>>((float*)d_out, nb);
}

// round 3
// speedup vs baseline: 1.2441x; 1.2441x over previous
#include <cuda_runtime.h>

#define THREADS 256
#define EPT     32                      // elements per thread (1 mask word)
#define CHUNK   (THREADS * EPT)         // 8192 elements per block
#define MAX_NB  32768
#define MAX_WORDS (1u << 20)            // supports n up to 32M
#define NWARPS  (THREADS / 32)

// Scratch (device globals — no allocations allowed)
__device__ unsigned g_cnt[MAX_NB];
__device__ unsigned g_off[MAX_NB];
__device__ unsigned g_total;
__device__ float    g_partial[MAX_NB];
__device__ unsigned g_mask[MAX_WORDS];
__device__ unsigned g_tickA = 0;
__device__ unsigned g_tickB = 0;

__device__ __forceinline__ unsigned warp_incl_scan(unsigned v) {
#pragma unroll
    for (int o = 1; o < 32; o <<= 1) {
        unsigned u = __shfl_up_sync(0xffffffffu, v, o);
        if ((threadIdx.x & 31) >= (unsigned)o) v += u;
    }
    return v;
}

// ---------------------------------------------------------------------------
// Kernel A: score -> packed bitmask + per-block counts; last block scans
// counts into g_off and computes g_total. Reads 64 MB, writes 2 MB.
// ---------------------------------------------------------------------------
__global__ void k_mask(const float* __restrict__ score, int n) {
    const int t = threadIdx.x;
    const int b = blockIdx.x;
    const long long w0 = (long long)b * THREADS + t;   // this thread's word
    const long long e0 = w0 * EPT;
    const long long nwords = ((long long)n + 31) >> 5;

    const float4* __restrict__ s4 = (const float4*)score;

    unsigned mask = 0;
    if (e0 + EPT - 1 < n) {
        float4 v[8];
#pragma unroll
        for (int i = 0; i < 8; i++) v[i] = __ldg(&s4[w0 * 8 + i]);
#pragma unroll
        for (int i = 0; i < 8; i++) {
            mask |= (v[i].x > 0.f ? 1u : 0u) << (i * 4 + 0);
            mask |= (v[i].y > 0.f ? 1u : 0u) << (i * 4 + 1);
            mask |= (v[i].z > 0.f ? 1u : 0u) << (i * 4 + 2);
            mask |= (v[i].w > 0.f ? 1u : 0u) << (i * 4 + 3);
        }
    } else {
#pragma unroll
        for (int j = 0; j < EPT; j++) {
            long long gi = e0 + j;
            if (gi < n && score[gi] > 0.f) mask |= 1u << j;
        }
    }
    if (w0 < nwords) g_mask[w0] = mask;

    // block reduce popcounts
    unsigned cnt = __popc(mask);
#pragma unroll
    for (int o = 16; o > 0; o >>= 1) cnt += __shfl_down_sync(0xffffffffu, cnt, o);
    __shared__ unsigned ws[NWARPS];
    __shared__ bool amlast;
    if ((t & 31) == 0) ws[t >> 5] = cnt;
    __syncthreads();
    if (t == 0) {
        unsigned s = 0;
#pragma unroll
        for (int w = 0; w < NWARPS; w++) s += ws[w];
        g_cnt[b] = s;
        __threadfence();
        unsigned tk = atomicAdd(&g_tickA, 1);
        amlast = (tk == gridDim.x - 1);
    }
    __syncthreads();
    if (!amlast) return;

    // ---- last block: scan g_cnt[0..nb) -> g_off, g_total ----
    const int nb = gridDim.x;
    const volatile unsigned* vcnt = g_cnt;
    __shared__ unsigned wsums[NWARPS];
    __shared__ unsigned wexcl[NWARPS];
    __shared__ unsigned tile_total;
    unsigned carry = 0;
    for (int tb = 0; tb < nb; tb += THREADS) {
        int i = tb + t;
        unsigned v = (i < nb) ? vcnt[i] : 0u;
        unsigned inc = warp_incl_scan(v);
        if ((t & 31) == 31) wsums[t >> 5] = inc;
        __syncthreads();
        if (t < 32) {
            unsigned x  = (t < NWARPS) ? wsums[t] : 0u;
            unsigned xi = warp_incl_scan(x);
            if (t < NWARPS) wexcl[t] = xi - x;
            if (t == NWARPS - 1) tile_total = xi;
        }
        __syncthreads();
        if (i < nb) g_off[i] = carry + wexcl[t >> 5] + (inc - v);
        carry += tile_total;
        __syncthreads();
    }
    if (t == 0) {
        g_total = carry;
        g_tickA = 0;          // self-reset for graph replay
    }
}

// ---------------------------------------------------------------------------
// Kernel B: pred + bitmask -> loss terms; last block does final reduce.
// Reads 66 MB.
// ---------------------------------------------------------------------------
__global__ void k_loss(const float* __restrict__ pred, float* __restrict__ out,
                       int n) {
    const int t = threadIdx.x;
    const int b = blockIdx.x;
    const long long w0 = (long long)b * THREADS + t;
    const long long e0 = w0 * EPT;
    const long long nwords = ((long long)n + 31) >> 5;

    const float4* __restrict__ p4 = (const float4*)pred;

    // issue all loads up-front (in flight during the scan below)
    unsigned mask = (w0 < nwords) ? g_mask[w0] : 0u;
    float4 v[8];
    if (e0 + EPT - 1 < n) {
#pragma unroll
        for (int i = 0; i < 8; i++) v[i] = __ldg(&p4[w0 * 8 + i]);
    } else {
        float* vf = (float*)v;
#pragma unroll
        for (int j = 0; j < EPT; j++) {
            long long gi = e0 + j;
            vf[j] = (gi < n) ? pred[gi] : 0.f;
        }
    }

    // block scan of per-thread popcounts (one scan per block)
    unsigned cnt = __popc(mask);
    unsigned inc = warp_incl_scan(cnt);
    __shared__ unsigned wsums[NWARPS];
    __shared__ unsigned wexcl[NWARPS];
    if ((t & 31) == 31) wsums[t >> 5] = inc;
    __syncthreads();
    if (t < 32) {
        unsigned x  = (t < NWARPS) ? wsums[t] : 0u;
        unsigned xi = warp_incl_scan(x);
        if (t < NWARPS) wexcl[t] = xi - x;
    }
    __syncthreads();

    unsigned kk = g_off[b] + wexcl[t >> 5] + (inc - cnt); // excl rank before e0

    const float Tf = (float)g_total;          // P, exact integer
    const float Sv = 1.0f / Tf;               // s at positives
    const float inv_sum_s = 1.0f / (Tf * Sv); // sum(s) ~ 1.0 (faithful)

    // negative denominator P+m+1 = Tf + (e0 + 2 - kk); increments by 1 per
    // negative. Always >= P (~8.4M) -> one RCP seed + Newton step per negative.
    float dstart = Tf + (float)(e0 + 2 - (long long)kk);
    float rn = __fdividef(1.0f, dstart);

    const float* pp = (const float*)v;
    float acc = 0.f;
#pragma unroll
    for (int j = 0; j < EPT; j++) {
        float p = pp[j] * inv_sum_s;
        if ((mask >> j) & 1u) {
            kk++;                                  // inclusive rank k
            float kf = (float)kk + 1.0f;           // k+1 >= 2
            float L  = __log2f(kf);
            float u  = __fdividef(1.0f, kf * L);
            float a  = (p * L - Sv * kf) * u;      // p/(k+1) - S/log2(k+1)
            acc = fmaf(a, a, acc);
        } else {
            float q = p * rn;                      // OOB: p==0 -> adds 0
            acc = fmaf(q, q, acc);
            rn = fmaf(-rn, rn, rn);                // 1/d -> 1/(d+1)
        }
    }

    // deterministic block reduce
#pragma unroll
    for (int o = 16; o > 0; o >>= 1) acc += __shfl_down_sync(0xffffffffu, acc, o);
    __shared__ float facc[NWARPS];
    __shared__ bool amlast;
    if ((t & 31) == 0) facc[t >> 5] = acc;
    __syncthreads();
    if (t == 0) {
        float s = 0.f;
#pragma unroll
        for (int w = 0; w < NWARPS; w++) s += facc[w];
        g_partial[b] = s;
        __threadfence();
        unsigned tk = atomicAdd(&g_tickB, 1);
        amlast = (tk == gridDim.x - 1);
    }
    __syncthreads();
    if (!amlast) return;

    // ---- last block: fixed-order final reduction ----
    const int nb = gridDim.x;
    const volatile float* vp = g_partial;
    float a = 0.f;
    for (int i = t; i < nb; i += THREADS) a += vp[i];
#pragma unroll
    for (int o = 16; o > 0; o >>= 1) a += __shfl_down_sync(0xffffffffu, a, o);
    __shared__ float sh[NWARPS];
    if ((t & 31) == 0) sh[t >> 5] = a;
    __syncthreads();
    if (t == 0) {
        float s = 0.f;
#pragma unroll
        for (int w = 0; w < NWARPS; w++) s += sh[w];
        out[0] = s;
        g_tickB = 0;          // self-reset for graph replay
    }
}

// ---------------------------------------------------------------------------
extern "C" void kernel_launch(void* const* d_in, const int* in_sizes, int n_in,
                              void* d_out, int out_size) {
    const float* pred  = (const float*)d_in[0];  // predict_score
    const float* score = (const float*)d_in[1];  // score
    int n  = in_sizes[0];
    int nb = (n + CHUNK - 1) / CHUNK;            // 2048 for N=16777216

    k_mask<<<nb, THREADS>>>(score, n);
    k_loss<<<nb, THREADS>>>(pred, (float*)d_out, n);
}

// round 4
// speedup vs baseline: 1.5827x; 1.2721x over previous
#include <cuda_runtime.h>

#define THREADS 256
#define NB      512                 // fixed grid; 512 <= 148*4 -> all resident
#define NWARPS  (THREADS / 32)
#define WPB_MAX 1280                // max words per block (n up to ~20.9M)

// Scratch (device globals — no allocations allowed)
__device__ unsigned g_cnt[NB];
__device__ float    g_partial[NB];
__device__ unsigned g_syncA = 0;    // phase-1 arrival
__device__ unsigned g_syncB = 0;    // phase-2 completion ticket

__device__ __forceinline__ unsigned warp_incl_scan(unsigned v) {
#pragma unroll
    for (int o = 1; o < 32; o <<= 1) {
        unsigned u = __shfl_up_sync(0xffffffffu, v, o);
        if ((threadIdx.x & 31) >= (unsigned)o) v += u;
    }
    return v;
}

__global__ __launch_bounds__(THREADS, 4)
void k_fused(const float* __restrict__ pred, const float* __restrict__ score,
             float* __restrict__ out, int n) {
    __shared__ unsigned s_mask[WPB_MAX];
    __shared__ unsigned s_excl[WPB_MAX];
    __shared__ unsigned s_w1[NWARPS];
    __shared__ unsigned s_w2[NWARPS];
    __shared__ float    s_f[NWARPS];
    __shared__ unsigned s_bcast[2];
    __shared__ bool     s_last;

    const int t = threadIdx.x;
    const int b = blockIdx.x;
    const long long nwords = ((long long)n + 31) >> 5;
    const int wpb = (int)((nwords + NB - 1) / NB);
    const long long wbase = (long long)b * wpb;

    // ------------------------------------------------------------------
    // Phase 1: positives bitmask -> smem (score read once: 64 MB)
    // ------------------------------------------------------------------
    const float4* __restrict__ s4 = (const float4*)score;
    for (int wl = t; wl < wpb; wl += THREADS) {
        long long gw = wbase + wl;
        unsigned mask = 0;
        if (gw < nwords) {
            long long e0 = gw << 5;
            if (e0 + 31 < n) {
                float4 v[8];
#pragma unroll
                for (int i = 0; i < 8; i++) v[i] = __ldg(&s4[gw * 8 + i]);
#pragma unroll
                for (int i = 0; i < 8; i++) {
                    mask |= (v[i].x > 0.f ? 1u : 0u) << (i * 4 + 0);
                    mask |= (v[i].y > 0.f ? 1u : 0u) << (i * 4 + 1);
                    mask |= (v[i].z > 0.f ? 1u : 0u) << (i * 4 + 2);
                    mask |= (v[i].w > 0.f ? 1u : 0u) << (i * 4 + 3);
                }
            } else {
#pragma unroll
                for (int j = 0; j < 32; j++) {
                    long long gi = e0 + j;
                    if (gi < n && score[gi] > 0.f) mask |= 1u << j;
                }
            }
        }
        s_mask[wl] = mask;
    }
    __syncthreads();

    // scan popcounts over wpb words -> per-word exclusive ranks (in-block)
    const int ipt = (wpb + THREADS - 1) / THREADS;
    const int lo = t * ipt;
    const int hi = (lo + ipt < wpb) ? lo + ipt : wpb;
    unsigned lsum = 0;
    for (int w = lo; w < hi; w++) lsum += __popc(s_mask[w]);
    unsigned inc = warp_incl_scan(lsum);
    if ((t & 31) == 31) s_w1[t >> 5] = inc;
    __syncthreads();
    if (t < 32) {
        unsigned x  = (t < NWARPS) ? s_w1[t] : 0u;
        unsigned xi = warp_incl_scan(x);
        if (t < NWARPS) s_w1[t] = xi - x;          // warp-exclusive
        if (t == NWARPS - 1) s_bcast[0] = xi;      // block total
    }
    __syncthreads();
    unsigned run = s_w1[t >> 5] + (inc - lsum);    // exclusive before thread
    for (int w = lo; w < hi; w++) {
        unsigned c = __popc(s_mask[w]);
        s_excl[w] = run;
        run += c;
    }
    if (t == 0) g_cnt[b] = s_bcast[0];
    __syncthreads();   // s_w1/s_bcast reuse below

    // ------------------------------------------------------------------
    // Grid-wide sync (all NB blocks resident by __launch_bounds__(256,4))
    // ------------------------------------------------------------------
    if (t == 0) {
        __threadfence();
        atomicAdd(&g_syncA, 1u);
        while (atomicAdd(&g_syncA, 0u) < NB) __nanosleep(64);
    }
    __syncthreads();

    // block offset (ranks before this block) + total positives P
    unsigned sum_before = 0, sum_total = 0;
    for (int i = t; i < NB; i += THREADS) {
        unsigned c = __ldcg(&g_cnt[i]);
        sum_total += c;
        if (i < b) sum_before += c;
    }
#pragma unroll
    for (int o = 16; o > 0; o >>= 1) {
        sum_before += __shfl_down_sync(0xffffffffu, sum_before, o);
        sum_total  += __shfl_down_sync(0xffffffffu, sum_total, o);
    }
    if ((t & 31) == 0) { s_w1[t >> 5] = sum_before; s_w2[t >> 5] = sum_total; }
    __syncthreads();
    if (t == 0) {
        unsigned a = 0, c = 0;
#pragma unroll
        for (int w = 0; w < NWARPS; w++) { a += s_w1[w]; c += s_w2[w]; }
        s_bcast[0] = a;   // block_off
        s_bcast[1] = c;   // P
    }
    __syncthreads();
    const unsigned block_off = s_bcast[0];
    const float Tf = (float)s_bcast[1];          // P, exact integer (< 2^24)
    const float Sv = 1.0f / Tf;                  // s at positives
    const float inv_sum_s = 1.0f / (Tf * Sv);    // sum(s) ~ 1.0 (faithful)

    // ------------------------------------------------------------------
    // Phase 2: branchless loss terms (pred read once: 64 MB)
    // ------------------------------------------------------------------
    const float4* __restrict__ p4 = (const float4*)pred;
    float acc = 0.f;

    for (int wl = t; wl < wpb; wl += THREADS) {
        long long gw = wbase + wl;
        if (gw >= nwords) break;
        long long e0 = gw << 5;
        unsigned mask = s_mask[wl];
        unsigned kk0  = block_off + s_excl[wl];   // exclusive rank before e0

        float4 v[8];
        if (e0 + 31 < n) {
#pragma unroll
            for (int i = 0; i < 8; i++) v[i] = __ldg(&p4[gw * 8 + i]);
        } else {
            float* vf = (float*)v;
#pragma unroll
            for (int j = 0; j < 32; j++) {
                long long gi = e0 + j;
                vf[j] = (gi < n) ? pred[gi] : 0.f;
            }
        }
        const float* pp = (const float*)v;

        float fk = (float)kk0 + 1.0f;             // = k_incl + 1 after += bf
        // neg denom D = P + m + 1 = C + j - k_incl; D steps +1 per negative
        float C  = Tf + (float)(e0 + 2);
        float rn = __fdividef(1.0f, C - (float)kk0);  // 1/D for first negative

#pragma unroll
        for (int j = 0; j < 32; j++) {
            unsigned bit = (mask >> j) & 1u;
            float bf = (float)bit;
            fk += bf;
            float p = pp[j] * inv_sum_s;
            // positive candidate: p/(k+1) - S/log2(k+1)  (junk if bit==0)
            float L = __log2f(fk);
            float u = __fdividef(1.0f, fk * L);
            float apos = fmaf(p, L, -(Sv * fk)) * u;
            // negative candidate
            float qn = p * rn;
            float val = bit ? apos : qn;
            acc = fmaf(val, val, acc);
            rn = fmaf((bf - 1.0f) * rn, rn, rn);  // 1/D -> 1/(D+1) on negatives
        }
    }

    // deterministic block reduce
#pragma unroll
    for (int o = 16; o > 0; o >>= 1) acc += __shfl_down_sync(0xffffffffu, acc, o);
    if ((t & 31) == 0) s_f[t >> 5] = acc;
    __syncthreads();
    if (t == 0) {
        float s = 0.f;
#pragma unroll
        for (int w = 0; w < NWARPS; w++) s += s_f[w];
        g_partial[b] = s;
        __threadfence();
        s_last = (atomicAdd(&g_syncB, 1u) == NB - 1);
    }
    __syncthreads();
    if (!s_last) return;

    // ---- last-finisher block: fixed-order final reduction ----
    float a = 0.f;
    for (int i = t; i < NB; i += THREADS) a += __ldcg(&g_partial[i]);
#pragma unroll
    for (int o = 16; o > 0; o >>= 1) a += __shfl_down_sync(0xffffffffu, a, o);
    if ((t & 31) == 0) s_f[t >> 5] = a;
    __syncthreads();
    if (t == 0) {
        float s = 0.f;
#pragma unroll
        for (int w = 0; w < NWARPS; w++) s += s_f[w];
        out[0] = s;
        g_syncA = 0;   // self-reset for graph replay (all blocks done)
        g_syncB = 0;
    }
}

// ---------------------------------------------------------------------------
extern "C" void kernel_launch(void* const* d_in, const int* in_sizes, int n_in,
                              void* d_out, int out_size) {
    const float* pred  = (const float*)d_in[0];  // predict_score
    const float* score = (const float*)d_in[1];  // score
    int n = in_sizes[0];
    k_fused<<<NB, THREADS>>>(pred, score, (float*)d_out, n);
}

// round 5
// speedup vs baseline: 1.6696x; 1.0549x over previous
#include <cuda_runtime.h>

#define THREADS 256
#define NB      296                 // = 148 SMs * 2 blocks -> all resident
#define NWARPS  (THREADS / 32)
#define WPB_MAX 2048                // max words per block (n up to ~19.4M)

// Scratch (device globals — no allocations allowed)
__device__ unsigned g_cnt[NB];
__device__ float    g_partial[NB];
__device__ unsigned g_syncA = 0;    // phase-1 arrival
__device__ unsigned g_syncB = 0;    // phase-2 completion ticket

__device__ __forceinline__ unsigned warp_incl_scan(unsigned v) {
#pragma unroll
    for (int o = 1; o < 32; o <<= 1) {
        unsigned u = __shfl_up_sync(0xffffffffu, v, o);
        if ((threadIdx.x & 31) >= (unsigned)o) v += u;
    }
    return v;
}

__global__ __launch_bounds__(THREADS, 2)
void k_fused(const float* __restrict__ pred, const float* __restrict__ score,
             float* __restrict__ out, int n) {
    __shared__ unsigned s_mask[WPB_MAX];
    __shared__ unsigned s_excl[WPB_MAX];
    __shared__ unsigned s_w1[NWARPS];
    __shared__ unsigned s_w2[NWARPS];
    __shared__ float    s_f[NWARPS];
    __shared__ unsigned s_bcast[2];
    __shared__ bool     s_last;

    const int t = threadIdx.x;
    const int b = blockIdx.x;
    const long long nwords = ((long long)n + 31) >> 5;
    const int wpb = (int)((nwords + NB - 1) / NB);
    const long long wbase = (long long)b * wpb;

    // ------------------------------------------------------------------
    // Phase 1: positives bitmask -> smem (score read once: 64 MB)
    // ------------------------------------------------------------------
    const float4* __restrict__ s4 = (const float4*)score;
    for (int wl = t; wl < wpb; wl += THREADS) {
        long long gw = wbase + wl;
        unsigned mask = 0;
        if (gw < nwords) {
            long long e0 = gw << 5;
            if (e0 + 31 < n) {
                float4 v[8];
#pragma unroll
                for (int i = 0; i < 8; i++) v[i] = __ldg(&s4[gw * 8 + i]);
#pragma unroll
                for (int i = 0; i < 8; i++) {
                    mask |= (v[i].x > 0.f ? 1u : 0u) << (i * 4 + 0);
                    mask |= (v[i].y > 0.f ? 1u : 0u) << (i * 4 + 1);
                    mask |= (v[i].z > 0.f ? 1u : 0u) << (i * 4 + 2);
                    mask |= (v[i].w > 0.f ? 1u : 0u) << (i * 4 + 3);
                }
            } else {
#pragma unroll
                for (int j = 0; j < 32; j++) {
                    long long gi = e0 + j;
                    if (gi < n && score[gi] > 0.f) mask |= 1u << j;
                }
            }
        }
        s_mask[wl] = mask;
    }
    __syncthreads();

    // scan popcounts over wpb words -> per-word exclusive ranks (in-block)
    const int ipt = (wpb + THREADS - 1) / THREADS;
    const int lo = t * ipt;
    const int hi = (lo + ipt < wpb) ? lo + ipt : wpb;
    unsigned lsum = 0;
    for (int w = lo; w < hi; w++) lsum += __popc(s_mask[w]);
    unsigned inc = warp_incl_scan(lsum);
    if ((t & 31) == 31) s_w1[t >> 5] = inc;
    __syncthreads();
    if (t < 32) {
        unsigned x  = (t < NWARPS) ? s_w1[t] : 0u;
        unsigned xi = warp_incl_scan(x);
        if (t < NWARPS) s_w1[t] = xi - x;          // warp-exclusive
        if (t == NWARPS - 1) s_bcast[0] = xi;      // block total
    }
    __syncthreads();
    unsigned run = s_w1[t >> 5] + (inc - lsum);    // exclusive before thread
    for (int w = lo; w < hi; w++) {
        unsigned c = __popc(s_mask[w]);
        s_excl[w] = run;
        run += c;
    }
    if (t == 0) g_cnt[b] = s_bcast[0];
    __syncthreads();   // s_w1/s_bcast reuse below

    // ------------------------------------------------------------------
    // Grid-wide sync (all NB blocks resident by __launch_bounds__(256,2))
    // ------------------------------------------------------------------
    if (t == 0) {
        __threadfence();
        atomicAdd(&g_syncA, 1u);
        while (atomicAdd(&g_syncA, 0u) < NB) __nanosleep(64);
    }
    __syncthreads();

    // block offset (ranks before this block) + total positives P
    unsigned sum_before = 0, sum_total = 0;
    for (int i = t; i < NB; i += THREADS) {
        unsigned c = __ldcg(&g_cnt[i]);
        sum_total += c;
        if (i < b) sum_before += c;
    }
#pragma unroll
    for (int o = 16; o > 0; o >>= 1) {
        sum_before += __shfl_down_sync(0xffffffffu, sum_before, o);
        sum_total  += __shfl_down_sync(0xffffffffu, sum_total, o);
    }
    if ((t & 31) == 0) { s_w1[t >> 5] = sum_before; s_w2[t >> 5] = sum_total; }
    __syncthreads();
    if (t == 0) {
        unsigned a = 0, c = 0;
#pragma unroll
        for (int w = 0; w < NWARPS; w++) { a += s_w1[w]; c += s_w2[w]; }
        s_bcast[0] = a;   // block_off
        s_bcast[1] = c;   // P
    }
    __syncthreads();
    const unsigned block_off = s_bcast[0];
    const float Tf = (float)s_bcast[1];          // P, exact integer (< 2^24)
    const float Sv = 1.0f / Tf;                  // s at positives
    const float inv_sum_s = 1.0f / (Tf * Sv);    // sum(s) ~ 1.0 (faithful)

    // ------------------------------------------------------------------
    // Phase 2: branchless loss terms (pred read once: 64 MB)
    // ------------------------------------------------------------------
    const float4* __restrict__ p4 = (const float4*)pred;
    float acc = 0.f;

    for (int wl = t; wl < wpb; wl += THREADS) {
        long long gw = wbase + wl;
        if (gw >= nwords) break;
        long long e0 = gw << 5;
        unsigned mask = s_mask[wl];
        unsigned kk0  = block_off + s_excl[wl];   // exclusive rank before e0

        float4 v[8];
        if (e0 + 31 < n) {
#pragma unroll
            for (int i = 0; i < 8; i++) v[i] = __ldg(&p4[gw * 8 + i]);
        } else {
            float* vf = (float*)v;
#pragma unroll
            for (int j = 0; j < 32; j++) {
                long long gi = e0 + j;
                vf[j] = (gi < n) ? pred[gi] : 0.f;
            }
        }
        const float* pp = (const float*)v;

        float fk = (float)kk0 + 1.0f;             // = k_incl + 1 after += bf
        // neg denom D = P + m + 1 = C + j - k_incl; D steps +1 per negative
        float C  = Tf + (float)(e0 + 2);
        float rn = __fdividef(1.0f, C - (float)kk0);  // 1/D for first negative

#pragma unroll
        for (int j = 0; j < 32; j++) {
            unsigned bit = (mask >> j) & 1u;
            float bf = (float)bit;
            fk += bf;
            float p = pp[j] * inv_sum_s;
            // positive candidate: p/(k+1) - S/log2(k+1)  (junk if bit==0)
            float L = __log2f(fk);
            float u = __fdividef(1.0f, fk * L);
            float apos = fmaf(p, L, -Sv * fk) * u;
            // negative candidate
            float qn = p * rn;
            float val = bit ? apos : qn;
            acc = fmaf(val, val, acc);
            rn = fmaf((bf - 1.0f) * rn, rn, rn);  // 1/D -> 1/(D+1) on negatives
        }
    }

    // deterministic block reduce
#pragma unroll
    for (int o = 16; o > 0; o >>= 1) acc += __shfl_down_sync(0xffffffffu, acc, o);
    if ((t & 31) == 0) s_f[t >> 5] = acc;
    __syncthreads();
    if (t == 0) {
        float s = 0.f;
#pragma unroll
        for (int w = 0; w < NWARPS; w++) s += s_f[w];
        g_partial[b] = s;
        __threadfence();
        s_last = (atomicAdd(&g_syncB, 1u) == NB - 1);
    }
    __syncthreads();
    if (!s_last) return;

    // ---- last-finisher block: fixed-order final reduction ----
    float a = 0.f;
    for (int i = t; i < NB; i += THREADS) a += __ldcg(&g_partial[i]);
#pragma unroll
    for (int o = 16; o > 0; o >>= 1) a += __shfl_down_sync(0xffffffffu, a, o);
    if ((t & 31) == 0) s_f[t >> 5] = a;
    __syncthreads();
    if (t == 0) {
        float s = 0.f;
#pragma unroll
        for (int w = 0; w < NWARPS; w++) s += s_f[w];
        out[0] = s;
        g_syncA = 0;   // self-reset for graph replay (all blocks done)
        g_syncB = 0;
    }
}

// ---------------------------------------------------------------------------
extern "C" void kernel_launch(void* const* d_in, const int* in_sizes, int n_in,
                              void* d_out, int out_size) {
    const float* pred  = (const float*)d_in[0];  // predict_score
    const float* score = (const float*)d_in[1];  // score
    int n = in_sizes[0];
    k_fused<<<NB, THREADS>>>(pred, score, (float*)d_out, n);
}